// round 17
// baseline (speedup 1.0000x reference)
#include <cuda_runtime.h>
#include <cstdint>

// Problem constants
#define BB   2
#define LL   4096
#define DD   768
#define HH   12
#define HDM  64
#define NBB  64
#define MLPD 3072
#define MTOT (BB * LL)            // 8192 rows

// Scratch layout (floats) inside one device buffer
#define SZ_BLD   (MTOT * DD)      // 6291456
#define OFF_H    0
#define OFF_Q    (1 * SZ_BLD)
#define OFF_K    (2 * SZ_BLD)
#define OFF_V    (3 * SZ_BLD)
#define OFF_O    (4 * SZ_BLD)
#define OFF_X1   (5 * SZ_BLD)
#define OFF_Y    (6 * SZ_BLD)
#define OFF_MLP  (7 * SZ_BLD)
#define SZ_MLP   (MTOT * MLPD)    // 25165824
#define BUF_TOTAL (7 * SZ_BLD + SZ_MLP)

__device__ float g_buf[BUF_TOTAL];
__device__ int   g_plan[62][8];

// ===========================================================================
// BigBird plan: bit-exact numpy legacy RandomState(0) reproduction
// ===========================================================================
__device__ __forceinline__ unsigned mt_next(unsigned* mt, int& mti) {
    if (mti >= 624) {
        for (int i = 0; i < 624; i++) {
            unsigned y = (mt[i] & 0x80000000u) | (mt[(i + 1) % 624] & 0x7fffffffu);
            mt[i] = mt[(i + 397) % 624] ^ (y >> 1) ^ ((y & 1u) ? 0x9908b0dfu : 0u);
        }
        mti = 0;
    }
    unsigned y = mt[mti++];
    y ^= y >> 11;
    y ^= (y << 7)  & 0x9d2c5680u;
    y ^= (y << 15) & 0xefc60000u;
    y ^= y >> 18;
    return y;
}

__device__ __forceinline__ unsigned rk_interval_dev(unsigned mx, unsigned* mt, int& mti) {
    if (mx == 0u) return 0u;
    unsigned mask = mx;
    mask |= mask >> 1; mask |= mask >> 2; mask |= mask >> 4;
    mask |= mask >> 8; mask |= mask >> 16;
    unsigned v;
    while ((v = (mt_next(mt, mti) & mask)) > mx) {}
    return v;
}

__global__ void plan_kernel() {
    __shared__ unsigned mt[624];
    if (threadIdx.x != 0) return;
    // rk_seed(0)
    unsigned seed = 0u;
    for (int pos = 0; pos < 624; pos++) {
        mt[pos] = seed;
        seed = 1812433253u * (seed ^ (seed >> 30)) + (unsigned)(pos + 1);
    }
    int mti = 624;

    for (int i = 1; i <= NBB - 2; i++) {
        int cand[60];
        int nc = 0;
        for (int j = 0; j < NBB; j++) {
            if (j == 0 || j == NBB - 1 || j == i - 1 || j == i || j == i + 1) continue;
            cand[nc++] = j;
        }
        // permutation(nc): Fisher-Yates, i from nc-1 down to 1
        int perm[60];
        for (int j = 0; j < nc; j++) perm[j] = j;
        for (int a = nc - 1; a > 0; a--) {
            int jj = (int)rk_interval_dev((unsigned)a, mt, mti);
            int t = perm[a]; perm[a] = perm[jj]; perm[jj] = t;
        }
        int row = i - 1;
        g_plan[row][0] = 0;
        g_plan[row][1] = NBB - 1;
        g_plan[row][2] = i - 1;
        g_plan[row][3] = i;
        g_plan[row][4] = i + 1;
        for (int r = 0; r < 3; r++) g_plan[row][5 + r] = cand[perm[r]];
    }
}

// ===========================================================================
// LayerNorm (two-pass, D=768, 256 threads per row)
// ===========================================================================
__device__ __forceinline__ float block_sum256(float v, float* red) {
    #pragma unroll
    for (int o = 16; o > 0; o >>= 1) v += __shfl_xor_sync(0xffffffffu, v, o);
    int lane = threadIdx.x & 31, w = threadIdx.x >> 5;
    __syncthreads();            // safe reuse of red across calls
    if (lane == 0) red[w] = v;
    __syncthreads();
    float r = (lane < 8) ? red[lane] : 0.0f;
    #pragma unroll
    for (int o = 16; o > 0; o >>= 1) r += __shfl_xor_sync(0xffffffffu, r, o);
    return r;
}

__global__ __launch_bounds__(256)
void layernorm_kernel(const float* __restrict__ x, const float* __restrict__ gam,
                      const float* __restrict__ bet, float* __restrict__ out) {
    __shared__ float red[32];
    const long row = blockIdx.x;
    const float* xr = x + row * DD;
    float* yr = out + row * DD;
    const int t = threadIdx.x;

    float a = xr[t], b = xr[t + 256], c = xr[t + 512];
    float total = block_sum256(a + b + c, red);
    float mu = total * (1.0f / (float)DD);
    float da = a - mu, db = b - mu, dc = c - mu;
    float tot2 = block_sum256(da * da + db * db + dc * dc, red);
    float rstd = rsqrtf(tot2 * (1.0f / (float)DD) + 1e-6f);

    yr[t]       = da * rstd * gam[t]       + bet[t];
    yr[t + 256] = db * rstd * gam[t + 256] + bet[t + 256];
    yr[t + 512] = dc * rstd * gam[t + 512] + bet[t + 512];
}

// ===========================================================================
// SGEMM: C[M,N] = alpha * A[M,K] @ B[K,N] (+bias)(+relu)(+residual)
// 128x128 tile, TK=8, 256 threads, 8x8 micro-tile
// epi flags: 1=bias, 2=relu, 4=residual
// ===========================================================================
__global__ __launch_bounds__(256)
void sgemm_kernel(const float* __restrict__ A, const float* __restrict__ B,
                  float* __restrict__ C, int M, int N, int K, float alpha,
                  const float* __restrict__ bias, const float* __restrict__ res,
                  int epi) {
    __shared__ float As[8 * 128];
    __shared__ float Bs[8 * 128];

    const int tid = threadIdx.x;
    const long m0 = (long)blockIdx.y * 128;
    const long n0 = (long)blockIdx.x * 128;

    const int rowb = (tid >> 4) << 3;   // 0..120
    const int colb = (tid & 15) << 3;   // 0..120
    const int arow = tid >> 1;          // 0..127
    const int acol = (tid & 1) << 2;    // 0 or 4
    const int brow = tid >> 5;          // 0..7
    const int bcol = (tid & 31) << 2;   // 0..124

    const float* Ap = A + (m0 + arow) * (long)K + acol;
    const float* Bp = B + (long)brow * N + n0 + bcol;

    float acc[8][8];
    #pragma unroll
    for (int i = 0; i < 8; i++)
        #pragma unroll
        for (int j = 0; j < 8; j++) acc[i][j] = 0.0f;

    for (int k0 = 0; k0 < K; k0 += 8) {
        float4 a4 = *(const float4*)(Ap + k0);
        float4 b4 = *(const float4*)(Bp + (long)k0 * N);
        As[(acol + 0) * 128 + arow] = a4.x;
        As[(acol + 1) * 128 + arow] = a4.y;
        As[(acol + 2) * 128 + arow] = a4.z;
        As[(acol + 3) * 128 + arow] = a4.w;
        *(float4*)&Bs[brow * 128 + bcol] = b4;
        __syncthreads();

        #pragma unroll
        for (int kk = 0; kk < 8; kk++) {
            float ar[8], br[8];
            *(float4*)&ar[0] = *(const float4*)&As[kk * 128 + rowb];
            *(float4*)&ar[4] = *(const float4*)&As[kk * 128 + rowb + 4];
            *(float4*)&br[0] = *(const float4*)&Bs[kk * 128 + colb];
            *(float4*)&br[4] = *(const float4*)&Bs[kk * 128 + colb + 4];
            #pragma unroll
            for (int i = 0; i < 8; i++)
                #pragma unroll
                for (int j = 0; j < 8; j++)
                    acc[i][j] = fmaf(ar[i], br[j], acc[i][j]);
        }
        __syncthreads();
    }

    float bv[8];
    if (epi & 1) {
        *(float4*)&bv[0] = *(const float4*)(bias + n0 + colb);
        *(float4*)&bv[4] = *(const float4*)(bias + n0 + colb + 4);
    }

    #pragma unroll
    for (int i = 0; i < 8; i++) {
        long roff = (m0 + rowb + i) * (long)N + n0 + colb;
        #pragma unroll
        for (int jb = 0; jb < 8; jb += 4) {
            float4 t;
            t.x = acc[i][jb + 0] * alpha;
            t.y = acc[i][jb + 1] * alpha;
            t.z = acc[i][jb + 2] * alpha;
            t.w = acc[i][jb + 3] * alpha;
            if (epi & 1) { t.x += bv[jb]; t.y += bv[jb + 1]; t.z += bv[jb + 2]; t.w += bv[jb + 3]; }
            if (epi & 2) {
                t.x = fmaxf(t.x, 0.0f); t.y = fmaxf(t.y, 0.0f);
                t.z = fmaxf(t.z, 0.0f); t.w = fmaxf(t.w, 0.0f);
            }
            if (epi & 4) {
                float4 r4 = *(const float4*)(res + roff + jb);
                t.x += r4.x; t.y += r4.y; t.z += r4.z; t.w += r4.w;
            }
            *(float4*)(C + roff + jb) = t;
        }
    }
}

// ===========================================================================
// BigBird attention: one CTA per (b, h, query block). Flash-style online
// softmax over key blocks (all 64 for global query blocks 0/63, else the
// 8 planned blocks, duplicates included — matching the reference gather).
// q/k/v/o layout: [B*L, H*HD] row-major (GEMM output layout).
// ===========================================================================
#define ATT_SMEM_FLOATS (4096 + 4160 + 4096 + 4096)

__global__ __launch_bounds__(256)
void attention_kernel(const float* __restrict__ q, const float* __restrict__ k,
                      const float* __restrict__ v, float* __restrict__ o) {
    extern __shared__ float sm[];
    float* Qs = sm;                         // [64][64]
    float* Ks = sm + 4096;                  // [64][65]  (padded: lane-varying row index)
    float* Vs = sm + 4096 + 4160;           // [64][64]
    float* Ps = sm + 4096 + 4160 + 4096;    // [64][64]

    const int qb = blockIdx.x, h = blockIdx.y, b = blockIdx.z;
    const int tid = threadIdx.x;
    const int tx = tid & 15, ty = tid >> 4;
    const int r0 = ty * 4, c0 = tx * 4;

    const long base_bh = (long)b * LL * DD + (long)h * HDM;

    // Load Q tile (already scaled by 1/8 in the Q GEMM)
    {
        const float* qp = q + base_bh + (long)qb * 64 * DD;
        for (int f = tid; f < 1024; f += 256) {
            int r = f >> 4, d4 = (f & 15) << 2;
            float4 t4 = *(const float4*)(qp + (long)r * DD + d4);
            *(float4*)&Qs[r * 64 + d4] = t4;
        }
    }

    float m_run[4], l_run[4], oacc[4][4];
    #pragma unroll
    for (int i = 0; i < 4; i++) {
        m_run[i] = -1e30f; l_run[i] = 0.0f;
        #pragma unroll
        for (int j = 0; j < 4; j++) oacc[i][j] = 0.0f;
    }

    const bool glob = (qb == 0) || (qb == NBB - 1);
    const int nk = glob ? NBB : 8;

    for (int it = 0; it < nk; it++) {
        const int kb = glob ? it : g_plan[qb - 1][it];
        __syncthreads();   // previous iteration's P·V reads done before reload

        const float* kp = k + base_bh + (long)kb * 64 * DD;
        const float* vp = v + base_bh + (long)kb * 64 * DD;
        for (int f = tid; f < 1024; f += 256) {
            int r = f >> 4, d4 = (f & 15) << 2;
            float4 kt = *(const float4*)(kp + (long)r * DD + d4);
            Ks[r * 65 + d4 + 0] = kt.x;
            Ks[r * 65 + d4 + 1] = kt.y;
            Ks[r * 65 + d4 + 2] = kt.z;
            Ks[r * 65 + d4 + 3] = kt.w;
            float4 vt = *(const float4*)(vp + (long)r * DD + d4);
            *(float4*)&Vs[r * 64 + d4] = vt;
        }
        __syncthreads();

        // S = Q K^T  (4x4 micro-tile per thread)
        float s[4][4];
        #pragma unroll
        for (int i = 0; i < 4; i++)
            #pragma unroll
            for (int j = 0; j < 4; j++) s[i][j] = 0.0f;

        #pragma unroll 8
        for (int d = 0; d < 64; d++) {
            float qv[4], kv[4];
            #pragma unroll
            for (int i = 0; i < 4; i++) qv[i] = Qs[(r0 + i) * 64 + d];
            #pragma unroll
            for (int j = 0; j < 4; j++) kv[j] = Ks[(c0 + j) * 65 + d];
            #pragma unroll
            for (int i = 0; i < 4; i++)
                #pragma unroll
                for (int j = 0; j < 4; j++)
                    s[i][j] = fmaf(qv[i], kv[j], s[i][j]);
        }

        // online softmax per query row (16 lanes with same ty share a row set)
        #pragma unroll
        for (int i = 0; i < 4; i++) {
            float mt = fmaxf(fmaxf(s[i][0], s[i][1]), fmaxf(s[i][2], s[i][3]));
            mt = fmaxf(mt, __shfl_xor_sync(0xffffffffu, mt, 8, 16));
            mt = fmaxf(mt, __shfl_xor_sync(0xffffffffu, mt, 4, 16));
            mt = fmaxf(mt, __shfl_xor_sync(0xffffffffu, mt, 2, 16));
            mt = fmaxf(mt, __shfl_xor_sync(0xffffffffu, mt, 1, 16));

            float mn = fmaxf(m_run[i], mt);
            float corr = __expf(m_run[i] - mn);
            m_run[i] = mn;

            float ls = 0.0f;
            #pragma unroll
            for (int j = 0; j < 4; j++) {
                float p = __expf(s[i][j] - mn);
                Ps[(r0 + i) * 64 + c0 + j] = p;
                ls += p;
            }
            ls += __shfl_xor_sync(0xffffffffu, ls, 8, 16);
            ls += __shfl_xor_sync(0xffffffffu, ls, 4, 16);
            ls += __shfl_xor_sync(0xffffffffu, ls, 2, 16);
            ls += __shfl_xor_sync(0xffffffffu, ls, 1, 16);

            l_run[i] = l_run[i] * corr + ls;
            #pragma unroll
            for (int j = 0; j < 4; j++) oacc[i][j] *= corr;
        }
        __syncthreads();

        // O += P V
        #pragma unroll 8
        for (int c = 0; c < 64; c++) {
            float pv[4], vv[4];
            #pragma unroll
            for (int i = 0; i < 4; i++) pv[i] = Ps[(r0 + i) * 64 + c];
            #pragma unroll
            for (int j = 0; j < 4; j++) vv[j] = Vs[c * 64 + c0 + j];
            #pragma unroll
            for (int i = 0; i < 4; i++)
                #pragma unroll
                for (int j = 0; j < 4; j++)
                    oacc[i][j] = fmaf(pv[i], vv[j], oacc[i][j]);
        }
    }

    float* op = o + base_bh + (long)qb * 64 * DD;
    #pragma unroll
    for (int i = 0; i < 4; i++) {
        float inv = 1.0f / l_run[i];
        #pragma unroll
        for (int j = 0; j < 4; j++)
            op[(long)(r0 + i) * DD + c0 + j] = oacc[i][j] * inv;
    }
}

// ===========================================================================
// Launcher
// ===========================================================================
extern "C" void kernel_launch(void* const* d_in, const int* in_sizes, int n_in,
                              void* d_out, int out_size) {
    (void)in_sizes; (void)n_in; (void)out_size;

    const float* x   = (const float*)d_in[0];
    const float* l1s = (const float*)d_in[1];
    const float* l1b = (const float*)d_in[2];
    const float* Wq  = (const float*)d_in[3];   // [D, H*HD] = [768,768]
    const float* Wk  = (const float*)d_in[4];
    const float* Wv  = (const float*)d_in[5];
    const float* Wo  = (const float*)d_in[6];   // [H*HD, D] = [768,768]
    const float* l2s = (const float*)d_in[7];
    const float* l2b = (const float*)d_in[8];
    const float* W1  = (const float*)d_in[9];   // [768, 3072]
    const float* b1  = (const float*)d_in[10];
    const float* W2  = (const float*)d_in[11];  // [3072, 768]
    const float* b2  = (const float*)d_in[12];
    float* out = (float*)d_out;

    float* buf = nullptr;
    cudaGetSymbolAddress((void**)&buf, g_buf);
    float* h   = buf + OFF_H;
    float* q   = buf + OFF_Q;
    float* k   = buf + OFF_K;
    float* v   = buf + OFF_V;
    float* o   = buf + OFF_O;
    float* x1  = buf + OFF_X1;
    float* y   = buf + OFF_Y;
    float* mlp = buf + OFF_MLP;

    const int att_smem = ATT_SMEM_FLOATS * (int)sizeof(float);
    cudaFuncSetAttribute(attention_kernel,
                         cudaFuncAttributeMaxDynamicSharedMemorySize, att_smem);

    const dim3 blk(256);
    const dim3 gNarrow(DD / 128, MTOT / 128);     // (6, 64)
    const dim3 gWide(MLPD / 128, MTOT / 128);     // (24, 64)

    // 1) BigBird key-block plan (bit-exact numpy RandomState(0))
    plan_kernel<<<1, 32>>>();

    // 2) LN1
    layernorm_kernel<<<MTOT, 256>>>(x, l1s, l1b, h);

    // 3) QKV projections (q pre-scaled by 1/sqrt(HD)=0.125)
    sgemm_kernel<<<gNarrow, blk>>>(h, Wq, q, MTOT, DD, DD, 0.125f, nullptr, nullptr, 0);
    sgemm_kernel<<<gNarrow, blk>>>(h, Wk, k, MTOT, DD, DD, 1.0f,   nullptr, nullptr, 0);
    sgemm_kernel<<<gNarrow, blk>>>(h, Wv, v, MTOT, DD, DD, 1.0f,   nullptr, nullptr, 0);

    // 4) BigBird attention
    attention_kernel<<<dim3(NBB, HH, BB), 256, att_smem>>>(q, k, v, o);

    // 5) Output projection + residual (x1 = attn + x)
    sgemm_kernel<<<gNarrow, blk>>>(o, Wo, x1, MTOT, DD, DD, 1.0f, nullptr, x, 4);

    // 6) LN2
    layernorm_kernel<<<MTOT, 256>>>(x1, l2s, l2b, y);

    // 7) MLP: relu(y@W1+b1) @ W2 + b2 + x1
    sgemm_kernel<<<gWide,   blk>>>(y,   W1, mlp, MTOT, MLPD, DD,   1.0f, b1, nullptr, 1 | 2);
    sgemm_kernel<<<gNarrow, blk>>>(mlp, W2, out, MTOT, DD,   MLPD, 1.0f, b2, x1,      1 | 4);
}